// round 6
// baseline (speedup 1.0000x reference)
#include <cuda_runtime.h>
#include <cuda_fp16.h>
#include <cstdint>

// Block-diagonal GEMM via mma.sync fp16 (f32 accum), fused A fp32->fp16 conversion.
// x:      [16384, 4096] fp32, logical [tokens, 8, 512]  (converted in-register at staging)
// blocks: [8, 512, 512] fp32 [k][n] -> pre-transposed fp16 [n][k] scratch g_bt16
// out[m, kb*512+n] = sum_k x[m, kb*512+k] * blocks[kb, k, n]

#define HIDDEN 4096
#define BLKD   512
#define NB     8
#define BM     128
#define BN     128
#define BK     64            // 64 halves = 128 B per smem row
#define NITER  (BLKD / BK)   // 8
#define NTH    256

#define ATILE  (BM * BK * 2)             // 16384 B
#define BTILE  (BN * BK * 2)             // 16384 B
#define SMEM_A(buf)  ((uint32_t)(buf) * ATILE)                 // 2 buffers
#define SMEM_B(stg)  (2u * ATILE + (uint32_t)(stg) * BTILE)    // 3 stages
#define SMEM_BYTES (2 * ATILE + 3 * BTILE)   // 81920

__device__ __half g_bt16[NB * BLKD * BLKD];  // [kb][n][k] fp16

#define SWZ(o) ((o) ^ (((o) >> 3) & 0x70))

static __device__ __forceinline__ uint32_t smem_u32(const void* p) {
    uint32_t a;
    asm("{ .reg .u64 t; cvta.to.shared.u64 t, %1; cvt.u32.u64 %0, t; }"
        : "=r"(a) : "l"(p));
    return a;
}

#define LDSM4(r0, r1, r2, r3, addr)                                          \
    asm volatile("ldmatrix.sync.aligned.m8n8.x4.shared.b16 {%0,%1,%2,%3}, [%4];" \
                 : "=r"(r0), "=r"(r1), "=r"(r2), "=r"(r3) : "r"(addr))

#define MMA_F16(c, a, b)                                                     \
    asm volatile("mma.sync.aligned.m16n8k16.row.col.f32.f16.f16.f32 "        \
                 "{%0,%1,%2,%3}, {%4,%5,%6,%7}, {%8,%9}, {%0,%1,%2,%3};"     \
                 : "+f"((c)[0]), "+f"((c)[1]), "+f"((c)[2]), "+f"((c)[3])    \
                 : "r"((a)[0]), "r"((a)[1]), "r"((a)[2]), "r"((a)[3]),       \
                   "r"((b)[0]), "r"((b)[1]))

#define CPASYNC16(dst, src)                                                  \
    asm volatile("cp.async.cg.shared.global [%0], [%1], 16;"                 \
                 :: "r"(dst), "l"(src) : "memory")

// ---------------- pre-pass: transpose + fp16 blocks -> [n][k] (4 MB, ~4 us) ----------------
__global__ void prep_b_kernel(const float* __restrict__ blocks) {
    __shared__ float tile[32][33];
    const int kb = blockIdx.z;
    const int k0 = blockIdx.x * 32, n0 = blockIdx.y * 32;
    const int tx = threadIdx.x, ty = threadIdx.y;  // 32 x 8
    #pragma unroll
    for (int i = 0; i < 32; i += 8)
        tile[ty + i][tx] = blocks[(size_t)kb * BLKD * BLKD + (size_t)(k0 + ty + i) * BLKD + n0 + tx];
    __syncthreads();
    #pragma unroll
    for (int i = 0; i < 32; i += 8)
        g_bt16[(size_t)kb * BLKD * BLKD + (size_t)(n0 + ty + i) * BLKD + k0 + tx] =
            __float2half_rn(tile[tx][ty + i]);
}

// ---------------- main GEMM ----------------
__global__ __launch_bounds__(NTH, 2)
void tpt_mma16_kernel(const float* __restrict__ x, float* __restrict__ out) {
    extern __shared__ __align__(1024) char smem[];
    const uint32_t sbase = smem_u32(smem);

    const int kb = blockIdx.z;
    const int m0 = blockIdx.x * BM;
    const int n0 = blockIdx.y * BN;
    const int tid = threadIdx.x;
    const int wid = tid >> 5, l = tid & 31;
    const int wm0 = (wid & 1) * 64;   // warp M offset
    const int wn0 = (wid >> 1) * 32;  // warp N offset

    // ---- A staging map: row = tid>>1 (0..127), half = tid&1 covers 32 fp32 (128 B) ----
    const int arow  = tid >> 1;
    const int ahalf = tid & 1;
    const float* Ag = x + (size_t)(m0 + arow) * HIDDEN + kb * BLKD + ahalf * 32;
    // STS target: A tile row arow (128 B fp16), byte col base ahalf*64
    const uint32_t a_sts0 = (uint32_t)(arow * 128 + ahalf * 64);

    // ---- B staging map: row rbase+32i, 16B-chunk q ----
    const int q = tid & 7;
    const int rbase = tid >> 3;
    const uint32_t b_swz = SWZ((uint32_t)(rbase * 128 + q * 16));  // +i*4096 safe
    const __half* Bg = g_bt16 + (size_t)kb * BLKD * BLKD + (size_t)(n0 + rbase) * BLKD + q * 8;

    float acc[4][4][4];
    #pragma unroll
    for (int mi = 0; mi < 4; mi++)
        #pragma unroll
        for (int nt = 0; nt < 4; nt++)
            #pragma unroll
            for (int r = 0; r < 4; r++) acc[mi][nt][r] = 0.0f;

    // ldmatrix per-lane address components (b16, 8x8 tile = 16B rows)
    const int mat = l >> 3;
    const int r8  = l & 7;
    const int a_rowadd = (mat & 1) * 8 + r8;
    const int a_colb   = (mat >> 1) * 16;
    const int b_rowadd = (mat >> 1) * 8 + r8;
    const int b_colb   = (mat & 1) * 16;

    auto issue_b = [&](int kt) {
        const uint32_t buf = sbase + SMEM_B(kt % 3) + b_swz;
        const __half* bsrc = Bg + (size_t)kt * BK;
        #pragma unroll
        for (int i = 0; i < 4; i++)
            CPASYNC16(buf + i * 4096u, bsrc + (size_t)i * 32 * BLKD);
        asm volatile("cp.async.commit_group;" ::: "memory");
    };

    float4 ra[8];
    auto ldg_a = [&](int kt) {
        const float4* src = reinterpret_cast<const float4*>(Ag + (size_t)kt * BK);
        #pragma unroll
        for (int i = 0; i < 8; i++) ra[i] = src[i];
    };
    auto sts_a = [&](int kt) {
        const uint32_t base = sbase + SMEM_A(kt & 1);
        #pragma unroll
        for (int c = 0; c < 4; c++) {
            __half2 h0 = __floats2half2_rn(ra[2 * c].x,     ra[2 * c].y);
            __half2 h1 = __floats2half2_rn(ra[2 * c].z,     ra[2 * c].w);
            __half2 h2 = __floats2half2_rn(ra[2 * c + 1].x, ra[2 * c + 1].y);
            __half2 h3 = __floats2half2_rn(ra[2 * c + 1].z, ra[2 * c + 1].w);
            asm volatile("st.shared.v4.b32 [%0], {%1,%2,%3,%4};"
                         :: "r"(base + SWZ(a_sts0 + (uint32_t)c * 16)),
                            "r"(*reinterpret_cast<uint32_t*>(&h0)),
                            "r"(*reinterpret_cast<uint32_t*>(&h1)),
                            "r"(*reinterpret_cast<uint32_t*>(&h2)),
                            "r"(*reinterpret_cast<uint32_t*>(&h3)) : "memory");
        }
    };

    // ---- prologue ----
    issue_b(0);
    ldg_a(0);

    #pragma unroll 1
    for (int kt = 0; kt < NITER; kt++) {
        sts_a(kt);                       // into A-buf kt%2 (last read: compute kt-2, done)
        if (kt + 1 < NITER) {
            issue_b(kt + 1);             // into B-stage (kt+1)%3 (last read: compute kt-2, done)
            ldg_a(kt + 1);               // LDG latency overlaps compute(kt)
            asm volatile("cp.async.wait_group 1;" ::: "memory");
        } else {
            asm volatile("cp.async.wait_group 0;" ::: "memory");
        }
        __syncthreads();                 // B(kt)+A(kt) visible; orders buffer reuse

        const uint32_t abase = sbase + SMEM_A(kt & 1);
        const uint32_t bbase = sbase + SMEM_B(kt % 3);
        #pragma unroll
        for (int ks = 0; ks < 4; ks++) {          // 4 x k16 steps
            uint32_t aF[4][4], bF[4][2];
            #pragma unroll
            for (int mi = 0; mi < 4; mi++) {
                uint32_t off = (uint32_t)((wm0 + mi * 16 + a_rowadd) * 128 + a_colb + ks * 32);
                LDSM4(aF[mi][0], aF[mi][1], aF[mi][2], aF[mi][3], abase + SWZ(off));
            }
            #pragma unroll
            for (int p = 0; p < 2; p++) {
                uint32_t off = (uint32_t)((wn0 + p * 16 + b_rowadd) * 128 + b_colb + ks * 32);
                LDSM4(bF[2 * p][0], bF[2 * p][1], bF[2 * p + 1][0], bF[2 * p + 1][1],
                      bbase + SWZ(off));
            }
            #pragma unroll
            for (int mi = 0; mi < 4; mi++)
                #pragma unroll
                for (int nt = 0; nt < 4; nt++)
                    MMA_F16(acc[mi][nt], aF[mi], bF[nt]);
        }
    }

    // ---- epilogue: direct float2 stores ----
    #pragma unroll
    for (int mi = 0; mi < 4; mi++) {
        const int grow = m0 + wm0 + mi * 16 + (l >> 2);
        #pragma unroll
        for (int nt = 0; nt < 4; nt++) {
            const int gcol = kb * BLKD + n0 + wn0 + nt * 8 + 2 * (l & 3);
            float2 v01 = make_float2(acc[mi][nt][0], acc[mi][nt][1]);
            float2 v23 = make_float2(acc[mi][nt][2], acc[mi][nt][3]);
            *reinterpret_cast<float2*>(out + (size_t)grow * HIDDEN + gcol) = v01;
            *reinterpret_cast<float2*>(out + (size_t)(grow + 8) * HIDDEN + gcol) = v23;
        }
    }
}

extern "C" void kernel_launch(void* const* d_in, const int* in_sizes, int n_in,
                              void* d_out, int out_size) {
    const float* x      = (const float*)d_in[0];
    const float* blocks = (const float*)d_in[1];
    float*       out    = (float*)d_out;

    const int M = in_sizes[0] / HIDDEN;  // 16384

    cudaFuncSetAttribute(tpt_mma16_kernel,
                         cudaFuncAttributeMaxDynamicSharedMemorySize, SMEM_BYTES);

    dim3 gp(BLKD / 32, BLKD / 32, NB), bp(32, 8);
    prep_b_kernel<<<gp, bp>>>(blocks);

    dim3 gg(M / BM, BLKD / BN, NB), bg(NTH);
    tpt_mma16_kernel<<<gg, bg, SMEM_BYTES>>>(x, out);
}

// round 9
// speedup vs baseline: 1.4897x; 1.4897x over previous
#include <cuda_runtime.h>
#include <cuda_fp16.h>
#include <cstdint>

// Block-diagonal GEMM, warp-specialized: 8 consumer warps (mma.sync fp16) +
// 4 producer warps (A fp32->fp16 LDG/cvt/STS + B cp.async), named-barrier pipeline.
// x:      [16384, 4096] fp32, logical [tokens, 8, 512]
// blocks: [8, 512, 512] fp32 [k][n] -> pre-transposed fp16 [n][k] scratch g_bt16
// out[m, kb*512+n] = sum_k x[m, kb*512+k] * blocks[kb, k, n]

#define HIDDEN 4096
#define BLKD   512
#define NB     8
#define BM     128
#define BN     128
#define BK     64            // 64 halves = 128 B per smem row
#define NITER  (BLKD / BK)   // 8
#define NCONS  256           // consumer threads (8 warps)
#define NPROD  128           // producer threads (4 warps)
#define NTH    (NCONS + NPROD)
#define STAGES 3

#define ATILE  (BM * BK * 2)             // 16384 B
#define BTILE  (BN * BK * 2)             // 16384 B
#define STAGEB (ATILE + BTILE)           // 32768
#define SMEM_BYTES (STAGES * STAGEB)     // 98304

// Named barrier ids: FULL = 1+s, EMPTY = 4+s  (s = 0..2)
#define BAR_SYNC(id)   asm volatile("bar.sync %0, %1;"   :: "r"(id), "r"(NTH) : "memory")
#define BAR_ARRIVE(id) asm volatile("bar.arrive %0, %1;" :: "r"(id), "r"(NTH) : "memory")

__device__ __half g_bt16[NB * BLKD * BLKD];  // [kb][n][k] fp16

#define SWZ(o) ((o) ^ (((o) >> 3) & 0x70))

static __device__ __forceinline__ uint32_t smem_u32(const void* p) {
    uint32_t a;
    asm("{ .reg .u64 t; cvta.to.shared.u64 t, %1; cvt.u32.u64 %0, t; }"
        : "=r"(a) : "l"(p));
    return a;
}

#define LDSM4(r0, r1, r2, r3, addr)                                          \
    asm volatile("ldmatrix.sync.aligned.m8n8.x4.shared.b16 {%0,%1,%2,%3}, [%4];" \
                 : "=r"(r0), "=r"(r1), "=r"(r2), "=r"(r3) : "r"(addr))

#define MMA_F16(c, a, b)                                                     \
    asm volatile("mma.sync.aligned.m16n8k16.row.col.f32.f16.f16.f32 "        \
                 "{%0,%1,%2,%3}, {%4,%5,%6,%7}, {%8,%9}, {%0,%1,%2,%3};"     \
                 : "+f"((c)[0]), "+f"((c)[1]), "+f"((c)[2]), "+f"((c)[3])    \
                 : "r"((a)[0]), "r"((a)[1]), "r"((a)[2]), "r"((a)[3]),       \
                   "r"((b)[0]), "r"((b)[1]))

#define CPASYNC16(dst, src)                                                  \
    asm volatile("cp.async.cg.shared.global [%0], [%1], 16;"                 \
                 :: "r"(dst), "l"(src) : "memory")

// ---------------- pre-pass: transpose + fp16 blocks -> [n][k] (4 MB) ----------------
__global__ void prep_b_kernel(const float* __restrict__ blocks) {
    __shared__ float tile[32][33];
    const int kb = blockIdx.z;
    const int k0 = blockIdx.x * 32, n0 = blockIdx.y * 32;
    const int tx = threadIdx.x, ty = threadIdx.y;  // 32 x 8
    #pragma unroll
    for (int i = 0; i < 32; i += 8)
        tile[ty + i][tx] = blocks[(size_t)kb * BLKD * BLKD + (size_t)(k0 + ty + i) * BLKD + n0 + tx];
    __syncthreads();
    #pragma unroll
    for (int i = 0; i < 32; i += 8)
        g_bt16[(size_t)kb * BLKD * BLKD + (size_t)(n0 + ty + i) * BLKD + k0 + tx] =
            __float2half_rn(tile[tx][ty + i]);
}

// ---------------- main GEMM (warp-specialized) ----------------
__global__ __launch_bounds__(NTH)
void tpt_ws_kernel(const float* __restrict__ x, float* __restrict__ out) {
    extern __shared__ __align__(1024) char smem[];
    const uint32_t sbase = smem_u32(smem);

    const int kb = blockIdx.z;
    const int n0 = blockIdx.x * BN;   // ntile on x: A-sharing CTAs adjacent in wave
    const int m0 = blockIdx.y * BM;
    const int tid = threadIdx.x;

    if (tid < NCONS) {
        // ================= CONSUMER =================
        const int wid = tid >> 5, l = tid & 31;
        const int wm0 = (wid & 1) * 64;
        const int wn0 = (wid >> 1) * 32;

        float acc[4][4][4];
        #pragma unroll
        for (int mi = 0; mi < 4; mi++)
            #pragma unroll
            for (int nt = 0; nt < 4; nt++)
                #pragma unroll
                for (int r = 0; r < 4; r++) acc[mi][nt][r] = 0.0f;

        const int mat = l >> 3;
        const int r8  = l & 7;
        const int a_rowadd = (mat & 1) * 8 + r8;
        const int a_colb   = (mat >> 1) * 16;
        const int b_rowadd = (mat >> 1) * 8 + r8;
        const int b_colb   = (mat & 1) * 16;

        #pragma unroll 1
        for (int kt = 0; kt < NITER; kt++) {
            const int s = kt % 3;
            BAR_SYNC(1 + s);  // wait FULL(s)

            const uint32_t abase = sbase + (uint32_t)s * STAGEB;
            const uint32_t bbase = abase + ATILE;
            #pragma unroll
            for (int ks = 0; ks < 4; ks++) {
                uint32_t aF[4][4], bF[4][2];
                #pragma unroll
                for (int mi = 0; mi < 4; mi++) {
                    uint32_t off = (uint32_t)((wm0 + mi * 16 + a_rowadd) * 128 + a_colb + ks * 32);
                    LDSM4(aF[mi][0], aF[mi][1], aF[mi][2], aF[mi][3], abase + SWZ(off));
                }
                #pragma unroll
                for (int p = 0; p < 2; p++) {
                    uint32_t off = (uint32_t)((wn0 + p * 16 + b_rowadd) * 128 + b_colb + ks * 32);
                    LDSM4(bF[2 * p][0], bF[2 * p][1], bF[2 * p + 1][0], bF[2 * p + 1][1],
                          bbase + SWZ(off));
                }
                #pragma unroll
                for (int mi = 0; mi < 4; mi++)
                    #pragma unroll
                    for (int nt = 0; nt < 4; nt++)
                        MMA_F16(acc[mi][nt], aF[mi], bF[nt]);
            }
            BAR_ARRIVE(4 + s);  // signal EMPTY(s)
        }

        // epilogue
        #pragma unroll
        for (int mi = 0; mi < 4; mi++) {
            const int grow = m0 + wm0 + mi * 16 + (l >> 2);
            #pragma unroll
            for (int nt = 0; nt < 4; nt++) {
                const int gcol = kb * BLKD + n0 + wn0 + nt * 8 + 2 * (l & 3);
                float2 v01 = make_float2(acc[mi][nt][0], acc[mi][nt][1]);
                float2 v23 = make_float2(acc[mi][nt][2], acc[mi][nt][3]);
                *reinterpret_cast<float2*>(out + (size_t)grow * HIDDEN + gcol) = v01;
                *reinterpret_cast<float2*>(out + (size_t)(grow + 8) * HIDDEN + gcol) = v23;
            }
        }
    } else {
        // ================= PRODUCER =================
        const int pid = tid - NCONS;  // 0..127

        // A map: row r0+8j (j=0..15), 16B fp32 chunk q -> 8B fp16 at SWZ(r*128 + q*8)
        const int ar0 = pid >> 4, aq = pid & 15;
        const float* Ags = x + (size_t)(m0 + ar0) * HIDDEN + kb * BLKD + aq * 4;
        const uint32_t a_sts = SWZ((uint32_t)(ar0 * 128 + aq * 8));   // + j*1024 safe

        // B map: row r0+16j (j=0..7), 16B chunk q
        const int br0 = pid >> 3, bq = pid & 7;
        const __half* Bgs = g_bt16 + (size_t)kb * BLKD * BLKD + (size_t)(n0 + br0) * BLKD + bq * 8;
        const uint32_t b_sts = SWZ((uint32_t)(br0 * 128 + bq * 16));  // + j*2048 safe

        #pragma unroll 1
        for (int kt = 0; kt < NITER; kt++) {
            const int s = kt % 3;
            if (kt >= STAGES) BAR_SYNC(4 + s);  // wait EMPTY(s)

            const uint32_t abuf = sbase + (uint32_t)s * STAGEB;
            const uint32_t bbuf = abuf + ATILE;

            // B: 8 cp.async (fire into this stage)
            const __half* bsrc = Bgs + (size_t)kt * BK;
            #pragma unroll
            for (int j = 0; j < 8; j++)
                CPASYNC16(bbuf + b_sts + (uint32_t)j * 2048u, bsrc + (size_t)j * 16 * BLKD);
            asm volatile("cp.async.commit_group;" ::: "memory");

            // A: 2 rounds of 8 (LDG.128 -> cvt -> STS.64)
            const float* asrc = Ags + (size_t)kt * BK;
            #pragma unroll
            for (int half = 0; half < 2; half++) {
                float4 ra[8];
                #pragma unroll
                for (int j = 0; j < 8; j++)
                    ra[j] = *reinterpret_cast<const float4*>(
                        asrc + (size_t)(half * 8 + j) * 8 * HIDDEN);
                #pragma unroll
                for (int j = 0; j < 8; j++) {
                    __half2 h0 = __floats2half2_rn(ra[j].x, ra[j].y);
                    __half2 h1 = __floats2half2_rn(ra[j].z, ra[j].w);
                    asm volatile("st.shared.v2.b32 [%0], {%1,%2};"
                                 :: "r"(abuf + a_sts + (uint32_t)(half * 8 + j) * 1024u),
                                    "r"(*reinterpret_cast<uint32_t*>(&h0)),
                                    "r"(*reinterpret_cast<uint32_t*>(&h1)) : "memory");
                }
            }

            asm volatile("cp.async.wait_group 0;" ::: "memory");  // B(kt) landed
            BAR_ARRIVE(1 + s);  // signal FULL(s)
        }
    }
}

extern "C" void kernel_launch(void* const* d_in, const int* in_sizes, int n_in,
                              void* d_out, int out_size) {
    const float* x      = (const float*)d_in[0];
    const float* blocks = (const float*)d_in[1];
    float*       out    = (float*)d_out;

    const int M = in_sizes[0] / HIDDEN;  // 16384

    cudaFuncSetAttribute(tpt_ws_kernel,
                         cudaFuncAttributeMaxDynamicSharedMemorySize, SMEM_BYTES);

    dim3 gp(BLKD / 32, BLKD / 32, NB), bp(32, 8);
    prep_b_kernel<<<gp, bp>>>(blocks);

    dim3 gg(BLKD / BN, M / BM, NB), bg(NTH);   // x = ntile (A reuse in-wave)
    tpt_ws_kernel<<<gg, bg, SMEM_BYTES>>>(x, out);
}

// round 12
// speedup vs baseline: 1.7360x; 1.1653x over previous
#include <cuda_runtime.h>
#include <cuda_fp16.h>
#include <cstdint>

// Block-diagonal GEMM, K-resident A with fused fp32->fp16 conversion.
// CTA: 64 M-rows x full K=512 (A in smem), loops 4 N-tiles of 128.
// B pipeline: 3-stage cp.async ring, 2 groups in flight (R5-proven discipline).
// x:      [16384, 4096] fp32, logical [tokens, 8, 512]
// blocks: [8, 512, 512] fp32 [k][n] -> pre-transposed fp16 [n][k] scratch g_bt16
// out[m, kb*512+n] = sum_k x[m, kb*512+k] * blocks[kb, k, n]

#define HIDDEN 4096
#define BLKD   512
#define NB     8
#define BM     64
#define BN     128
#define BK     64               // k-chunk: 64 halves = 128 B rows
#define NKC    (BLKD / BK)      // 8 chunks
#define NT4    (BLKD / BN)      // 4 n-tiles
#define NSTEP  (NT4 * NKC)      // 32 pipeline steps
#define NTH    256
#define BSTG   3                // B ring stages

#define ACH    (BM * BK * 2)    // A chunk bytes: 8192
#define ABYTES (NKC * ACH)      // 65536 (full-K A)
#define BTILE  (BN * BK * 2)    // 16384
#define SMEM_B_OFF ABYTES
#define SMEM_BYTES (ABYTES + BSTG * BTILE)   // 114688

__device__ __half g_bt16[NB * BLKD * BLKD];  // [kb][n][k] fp16

#define SWZ(o) ((o) ^ (((o) >> 3) & 0x70))

static __device__ __forceinline__ uint32_t smem_u32(const void* p) {
    uint32_t a;
    asm("{ .reg .u64 t; cvta.to.shared.u64 t, %1; cvt.u32.u64 %0, t; }"
        : "=r"(a) : "l"(p));
    return a;
}

#define LDSM4(r0, r1, r2, r3, addr)                                          \
    asm volatile("ldmatrix.sync.aligned.m8n8.x4.shared.b16 {%0,%1,%2,%3}, [%4];" \
                 : "=r"(r0), "=r"(r1), "=r"(r2), "=r"(r3) : "r"(addr))

#define MMA_F16(c, a, b)                                                     \
    asm volatile("mma.sync.aligned.m16n8k16.row.col.f32.f16.f16.f32 "        \
                 "{%0,%1,%2,%3}, {%4,%5,%6,%7}, {%8,%9}, {%0,%1,%2,%3};"     \
                 : "+f"((c)[0]), "+f"((c)[1]), "+f"((c)[2]), "+f"((c)[3])    \
                 : "r"((a)[0]), "r"((a)[1]), "r"((a)[2]), "r"((a)[3]),       \
                   "r"((b)[0]), "r"((b)[1]))

#define CPASYNC16(dst, src)                                                  \
    asm volatile("cp.async.cg.shared.global [%0], [%1], 16;"                 \
                 :: "r"(dst), "l"(src) : "memory")

// ---------------- pre-pass: transpose + fp16 blocks -> [n][k] (4 MB) ----------------
__global__ void prep_b_kernel(const float* __restrict__ blocks) {
    __shared__ float tile[32][33];
    const int kb = blockIdx.z;
    const int k0 = blockIdx.x * 32, n0 = blockIdx.y * 32;
    const int tx = threadIdx.x, ty = threadIdx.y;  // 32 x 8
    #pragma unroll
    for (int i = 0; i < 32; i += 8)
        tile[ty + i][tx] = blocks[(size_t)kb * BLKD * BLKD + (size_t)(k0 + ty + i) * BLKD + n0 + tx];
    __syncthreads();
    #pragma unroll
    for (int i = 0; i < 32; i += 8)
        g_bt16[(size_t)kb * BLKD * BLKD + (size_t)(n0 + ty + i) * BLKD + k0 + tx] =
            __float2half_rn(tile[tx][ty + i]);
}

// ---------------- main GEMM ----------------
__global__ __launch_bounds__(NTH, 2)
void tpt_kres_kernel(const float* __restrict__ x, float* __restrict__ out) {
    extern __shared__ __align__(1024) char smem[];
    const uint32_t sbase = smem_u32(smem);

    const int kb = blockIdx.z;
    const int m0 = blockIdx.x * BM;     // consecutive CTAs share kb -> B L2 reuse
    const int tid = threadIdx.x;
    const int wid = tid >> 5, l = tid & 31;
    const int wm0 = (wid & 1) * 32;     // warp: 32 M x 32 N
    const int wn0 = (wid >> 1) * 32;

    // ---- B staging map: row rbase+32j (j=0..3), 16B chunk q ----
    const int q = tid & 7;
    const int rbase = tid >> 3;
    const uint32_t b_swz = SWZ((uint32_t)(rbase * 128 + q * 16));  // + j*4096 safe
    const __half* Bg = g_bt16 + (size_t)kb * BLKD * BLKD + (size_t)rbase * BLKD + q * 8;

    auto issue_b = [&](int s) {  // step s: nt = s>>3, kc = s&7
        const int nt = s >> 3, kc = s & 7;
        const uint32_t buf = sbase + SMEM_B_OFF + (uint32_t)(s % BSTG) * BTILE + b_swz;
        const __half* src = Bg + (size_t)(nt * BN) * BLKD + kc * BK;
        #pragma unroll
        for (int j = 0; j < 4; j++)
            CPASYNC16(buf + (uint32_t)j * 4096u, src + (size_t)j * 32 * BLKD);
        asm volatile("cp.async.commit_group;" ::: "memory");
    };

    // prologue: two B groups in flight BEFORE any waiting
    issue_b(0);
    issue_b(1);

    // ================= phase 1: A fp32 -> fp16 into smem (full K) =================
    // thread -> row ar (0..63), quarter aq (0..3); covers k = kc*64 + t*16 + aq*4
    {
        const int ar = tid >> 2, aq = tid & 3;
        const float* Ap = x + (size_t)(m0 + ar) * HIDDEN + kb * BLKD + aq * 4;
        const uint32_t srow = (uint32_t)(ar * 128 + aq * 8);
        #pragma unroll
        for (int kc = 0; kc < NKC; kc++) {
            #pragma unroll
            for (int t = 0; t < 4; t++) {
                float4 v = *reinterpret_cast<const float4*>(Ap + kc * 64 + t * 16);
                __half2 h0 = __floats2half2_rn(v.x, v.y);
                __half2 h1 = __floats2half2_rn(v.z, v.w);
                asm volatile("st.shared.v2.b32 [%0], {%1,%2};"
                             :: "r"(sbase + (uint32_t)kc * ACH + SWZ(srow + (uint32_t)t * 32)),
                                "r"(*reinterpret_cast<uint32_t*>(&h0)),
                                "r"(*reinterpret_cast<uint32_t*>(&h1)) : "memory");
            }
        }
    }

    // ldmatrix per-lane components
    const int mat = l >> 3;
    const int r8  = l & 7;
    const int a_rowadd = (mat & 1) * 8 + r8;
    const int a_colb   = (mat >> 1) * 16;
    const int b_rowadd = (mat >> 1) * 8 + r8;
    const int b_colb   = (mat & 1) * 16;

    float acc[2][4][4];
    #pragma unroll
    for (int mi = 0; mi < 2; mi++)
        #pragma unroll
        for (int nt = 0; nt < 4; nt++)
            #pragma unroll
            for (int r = 0; r < 4; r++) acc[mi][nt][r] = 0.0f;

    #pragma unroll 1
    for (int s = 0; s < NSTEP; s++) {
        if (s + 1 < NSTEP) {
            asm volatile("cp.async.wait_group 1;" ::: "memory");  // B(s) complete (2 in flight)
        } else {
            asm volatile("cp.async.wait_group 0;" ::: "memory");
        }
        __syncthreads();          // B(s) visible to all; s==0 also publishes A phase
        if (s + 2 < NSTEP) issue_b(s + 2);  // ring stage (s+2)%3: last read at compute(s-1), done

        const int kc = s & 7;
        const uint32_t abase = sbase + (uint32_t)kc * ACH;
        const uint32_t bbase = sbase + SMEM_B_OFF + (uint32_t)(s % BSTG) * BTILE;
        #pragma unroll
        for (int ks = 0; ks < 4; ks++) {          // 4 x k16 steps per chunk
            uint32_t aF[2][4], bF[4][2];
            #pragma unroll
            for (int mi = 0; mi < 2; mi++) {
                uint32_t off = (uint32_t)((wm0 + mi * 16 + a_rowadd) * 128 + a_colb + ks * 32);
                LDSM4(aF[mi][0], aF[mi][1], aF[mi][2], aF[mi][3], abase + SWZ(off));
            }
            #pragma unroll
            for (int p = 0; p < 2; p++) {
                uint32_t off = (uint32_t)((wn0 + p * 16 + b_rowadd) * 128 + b_colb + ks * 32);
                LDSM4(bF[2 * p][0], bF[2 * p][1], bF[2 * p + 1][0], bF[2 * p + 1][1],
                      bbase + SWZ(off));
            }
            #pragma unroll
            for (int mi = 0; mi < 2; mi++)
                #pragma unroll
                for (int nt = 0; nt < 4; nt++)
                    MMA_F16(acc[mi][nt], aF[mi], bF[nt]);
        }

        // n-tile finished? store + reset acc
        if (kc == 7) {
            const int nt4 = s >> 3;
            #pragma unroll
            for (int mi = 0; mi < 2; mi++) {
                const int grow = m0 + wm0 + mi * 16 + (l >> 2);
                #pragma unroll
                for (int nt = 0; nt < 4; nt++) {
                    const int gcol = kb * BLKD + nt4 * BN + wn0 + nt * 8 + 2 * (l & 3);
                    float2 v01 = make_float2(acc[mi][nt][0], acc[mi][nt][1]);
                    float2 v23 = make_float2(acc[mi][nt][2], acc[mi][nt][3]);
                    *reinterpret_cast<float2*>(out + (size_t)grow * HIDDEN + gcol) = v01;
                    *reinterpret_cast<float2*>(out + (size_t)(grow + 8) * HIDDEN + gcol) = v23;
                    acc[mi][nt][0] = acc[mi][nt][1] = acc[mi][nt][2] = acc[mi][nt][3] = 0.0f;
                }
            }
        }
    }
}

extern "C" void kernel_launch(void* const* d_in, const int* in_sizes, int n_in,
                              void* d_out, int out_size) {
    const float* x      = (const float*)d_in[0];
    const float* blocks = (const float*)d_in[1];
    float*       out    = (float*)d_out;

    const int M = in_sizes[0] / HIDDEN;  // 16384

    cudaFuncSetAttribute(tpt_kres_kernel,
                         cudaFuncAttributeMaxDynamicSharedMemorySize, SMEM_BYTES);

    dim3 gp(BLKD / 32, BLKD / 32, NB), bp(32, 8);
    prep_b_kernel<<<gp, bp>>>(blocks);

    dim3 gg(M / BM, 1, NB), bg(NTH);
    tpt_kres_kernel<<<gg, bg, SMEM_BYTES>>>(x, out);
}

// round 13
// speedup vs baseline: 1.8046x; 1.0395x over previous
#include <cuda_runtime.h>
#include <cuda_fp16.h>
#include <cstdint>

// Block-diagonal GEMM via mma.sync fp16 (f32 accum): R5 two-kernel split with
// higher occupancy (BM=64 tiles, 3 CTAs/SM).
// x:      [16384, 4096] fp32 -> pre-converted fp16 scratch g_xh (prep_a, HBM-bound)
// blocks: [8, 512, 512] fp32 [k][n] -> pre-transposed fp16 [n][k] scratch g_bt16
// out[m, kb*512+n] = sum_k x[m, kb*512+k] * blocks[kb, k, n]

#define HIDDEN 4096
#define BLKD   512
#define NB     8
#define BM     64
#define BN     128
#define BK     64            // 64 halves = 128 B per smem row
#define NITER  (BLKD / BK)   // 8
#define NTH    256
#define STAGES 3

#define ABYTES (BM * BK * 2)             // 8192
#define BBYTES (BN * BK * 2)             // 16384
#define BUFBYTES (ABYTES + BBYTES)       // 24576
#define SMEM_BYTES (STAGES * BUFBYTES)   // 73728

__device__ __half g_xh[16384 * HIDDEN];      // 134 MB fp16 x
__device__ __half g_bt16[NB * BLKD * BLKD];  // 4 MB, [kb][n][k]

#define SWZ(o) ((o) ^ (((o) >> 3) & 0x70))

static __device__ __forceinline__ uint32_t smem_u32(const void* p) {
    uint32_t a;
    asm("{ .reg .u64 t; cvta.to.shared.u64 t, %1; cvt.u32.u64 %0, t; }"
        : "=r"(a) : "l"(p));
    return a;
}

#define LDSM4(r0, r1, r2, r3, addr)                                          \
    asm volatile("ldmatrix.sync.aligned.m8n8.x4.shared.b16 {%0,%1,%2,%3}, [%4];" \
                 : "=r"(r0), "=r"(r1), "=r"(r2), "=r"(r3) : "r"(addr))

#define MMA_F16(c, a, b)                                                     \
    asm volatile("mma.sync.aligned.m16n8k16.row.col.f32.f16.f16.f32 "        \
                 "{%0,%1,%2,%3}, {%4,%5,%6,%7}, {%8,%9}, {%0,%1,%2,%3};"     \
                 : "+f"((c)[0]), "+f"((c)[1]), "+f"((c)[2]), "+f"((c)[3])    \
                 : "r"((a)[0]), "r"((a)[1]), "r"((a)[2]), "r"((a)[3]),       \
                   "r"((b)[0]), "r"((b)[1]))

#define CPASYNC16(dst, src)                                                  \
    asm volatile("cp.async.cg.shared.global [%0], [%1], 16;"                 \
                 :: "r"(dst), "l"(src) : "memory")

// ---------------- pre-pass 1: x fp32 -> fp16 (HBM-bound, ~55 us) ----------------
__global__ __launch_bounds__(256)
void prep_a_kernel(const float* __restrict__ x, long long n8) {
    long long i = (long long)blockIdx.x * 256 + threadIdx.x;  // one i = 8 elements
    if (i >= n8) return;
    const float4* src = reinterpret_cast<const float4*>(x) + 2 * i;
    float4 v0 = src[0], v1 = src[1];
    __half2 h0 = __floats2half2_rn(v0.x, v0.y);
    __half2 h1 = __floats2half2_rn(v0.z, v0.w);
    __half2 h2 = __floats2half2_rn(v1.x, v1.y);
    __half2 h3 = __floats2half2_rn(v1.z, v1.w);
    uint4 o;
    o.x = *reinterpret_cast<uint32_t*>(&h0);
    o.y = *reinterpret_cast<uint32_t*>(&h1);
    o.z = *reinterpret_cast<uint32_t*>(&h2);
    o.w = *reinterpret_cast<uint32_t*>(&h3);
    reinterpret_cast<uint4*>(g_xh)[i] = o;
}

// ---------------- pre-pass 2: transpose + fp16 blocks -> [n][k] ----------------
__global__ void prep_b_kernel(const float* __restrict__ blocks) {
    __shared__ float tile[32][33];
    const int kb = blockIdx.z;
    const int k0 = blockIdx.x * 32, n0 = blockIdx.y * 32;
    const int tx = threadIdx.x, ty = threadIdx.y;  // 32 x 8
    #pragma unroll
    for (int i = 0; i < 32; i += 8)
        tile[ty + i][tx] = blocks[(size_t)kb * BLKD * BLKD + (size_t)(k0 + ty + i) * BLKD + n0 + tx];
    __syncthreads();
    #pragma unroll
    for (int i = 0; i < 32; i += 8)
        g_bt16[(size_t)kb * BLKD * BLKD + (size_t)(n0 + ty + i) * BLKD + k0 + tx] =
            __float2half_rn(tile[tx][ty + i]);
}

// ---------------- main GEMM ----------------
__global__ __launch_bounds__(NTH, 3)
void tpt_mma16_kernel(float* __restrict__ out) {
    extern __shared__ __align__(1024) char smem[];
    const uint32_t sbase = smem_u32(smem);

    const int kb = blockIdx.z;
    const int n0 = blockIdx.x * BN;   // n fastest: 4 A-sharing CTAs adjacent in wave
    const int m0 = blockIdx.y * BM;
    const int tid = threadIdx.x;
    const int wid = tid >> 5, l = tid & 31;
    const int wm0 = (wid & 1) * 32;   // warp tile 32 M x 32 N
    const int wn0 = (wid >> 1) * 32;

    // staging maps (16B chunks): q = tid&7, rbase = tid>>3 (0..31)
    const int q = tid & 7;
    const int rbase = tid >> 3;
    const uint32_t stg_swz = SWZ((uint32_t)(rbase * 128 + q * 16));  // +j*4096 safe

    const __half* Ag = g_xh + (size_t)(m0 + rbase) * HIDDEN + kb * BLKD + q * 8;
    const __half* Bg = g_bt16 + (size_t)kb * BLKD * BLKD + (size_t)(n0 + rbase) * BLKD + q * 8;

    float acc[2][4][4];
    #pragma unroll
    for (int mi = 0; mi < 2; mi++)
        #pragma unroll
        for (int nt = 0; nt < 4; nt++)
            #pragma unroll
            for (int r = 0; r < 4; r++) acc[mi][nt][r] = 0.0f;

    // ldmatrix per-lane address components
    const int mat = l >> 3;
    const int r8  = l & 7;
    const int a_rowadd = (mat & 1) * 8 + r8;
    const int a_colb   = (mat >> 1) * 16;
    const int b_rowadd = (mat >> 1) * 8 + r8;
    const int b_colb   = (mat & 1) * 16;

    auto issue_stage = [&](int kt) {
        const uint32_t buf = sbase + (uint32_t)(kt % STAGES) * BUFBYTES;
        const __half* asrc = Ag + (size_t)kt * BK;
        const __half* bsrc = Bg + (size_t)kt * BK;
        // A tile: 64 rows -> rows rbase, rbase+32
        #pragma unroll
        for (int j = 0; j < 2; j++)
            CPASYNC16(buf + stg_swz + j * 4096u, asrc + (size_t)j * 32 * HIDDEN);
        // B tile: 128 rows -> rbase + 32j
        #pragma unroll
        for (int j = 0; j < 4; j++)
            CPASYNC16(buf + ABYTES + stg_swz + j * 4096u, bsrc + (size_t)j * 32 * BLKD);
        asm volatile("cp.async.commit_group;" ::: "memory");
    };

    issue_stage(0);
    issue_stage(1);

    #pragma unroll 1
    for (int kt = 0; kt < NITER; kt++) {
        if (kt + 1 < NITER) {
            asm volatile("cp.async.wait_group 1;" ::: "memory");
        } else {
            asm volatile("cp.async.wait_group 0;" ::: "memory");
        }
        __syncthreads();  // stage(kt) visible; orders buffer reuse for issue below

        if (kt + 2 < NITER) issue_stage(kt + 2);

        const uint32_t abase = sbase + (uint32_t)(kt % STAGES) * BUFBYTES;
        const uint32_t bbase = abase + ABYTES;
        #pragma unroll
        for (int ks = 0; ks < 4; ks++) {          // 4 x k16 steps (BK=64)
            uint32_t aF[2][4], bF[4][2];
            #pragma unroll
            for (int mi = 0; mi < 2; mi++) {
                uint32_t off = (uint32_t)((wm0 + mi * 16 + a_rowadd) * 128 + a_colb + ks * 32);
                LDSM4(aF[mi][0], aF[mi][1], aF[mi][2], aF[mi][3], abase + SWZ(off));
            }
            #pragma unroll
            for (int p = 0; p < 2; p++) {
                uint32_t off = (uint32_t)((wn0 + p * 16 + b_rowadd) * 128 + b_colb + ks * 32);
                LDSM4(bF[2 * p][0], bF[2 * p][1], bF[2 * p + 1][0], bF[2 * p + 1][1],
                      bbase + SWZ(off));
            }
            #pragma unroll
            for (int mi = 0; mi < 2; mi++)
                #pragma unroll
                for (int nt = 0; nt < 4; nt++)
                    MMA_F16(acc[mi][nt], aF[mi], bF[nt]);
        }
    }

    // ---- epilogue: direct float2 stores ----
    #pragma unroll
    for (int mi = 0; mi < 2; mi++) {
        const int grow = m0 + wm0 + mi * 16 + (l >> 2);
        #pragma unroll
        for (int nt = 0; nt < 4; nt++) {
            const int gcol = kb * BLKD + n0 + wn0 + nt * 8 + 2 * (l & 3);
            float2 v01 = make_float2(acc[mi][nt][0], acc[mi][nt][1]);
            float2 v23 = make_float2(acc[mi][nt][2], acc[mi][nt][3]);
            *reinterpret_cast<float2*>(out + (size_t)grow * HIDDEN + gcol) = v01;
            *reinterpret_cast<float2*>(out + (size_t)(grow + 8) * HIDDEN + gcol) = v23;
        }
    }
}

extern "C" void kernel_launch(void* const* d_in, const int* in_sizes, int n_in,
                              void* d_out, int out_size) {
    const float* x      = (const float*)d_in[0];
    const float* blocks = (const float*)d_in[1];
    float*       out    = (float*)d_out;

    const int M = in_sizes[0] / HIDDEN;  // 16384
    const long long n8 = (long long)M * HIDDEN / 8;

    cudaFuncSetAttribute(tpt_mma16_kernel,
                         cudaFuncAttributeMaxDynamicSharedMemorySize, SMEM_BYTES);

    prep_a_kernel<<<(unsigned)((n8 + 255) / 256), 256>>>(x, n8);

    dim3 gp(BLKD / 32, BLKD / 32, NB), bp(32, 8);
    prep_b_kernel<<<gp, bp>>>(blocks);

    dim3 gg(BLKD / BN, M / BM, NB), bg(NTH);  // x = ntile (A L2 reuse in-wave)
    tpt_mma16_kernel<<<gg, bg, SMEM_BYTES>>>(out);
}